// round 6
// baseline (speedup 1.0000x reference)
#include <cuda_runtime.h>
#include <cuda_fp16.h>
#include <cstdint>

// ---------------------------------------------------------------------------
// MoE (AriaExperts): top-2 routing + grouped GEMM (SwiGLU fused) + combine
// tokens=2048, hidden=1024, inter=2048, experts=8, topk=2
//
// Dual-path GEMM: tcgen05 (arch-specific pass) with mma.sync fallback
// (generic pass). Same kernel symbols / launch geometry for both.
// tcgen05 B tiles are K-major [N,K] SW128 (transposed during SMEM fill) —
// the exact descriptor configuration validated by test_2cta_mma_bf16.
// ---------------------------------------------------------------------------

#if defined(__CUDA_ARCH__) && \
    (defined(__CUDA_ARCH_FEAT_SM103_ALL) || \
     (defined(__CUDA_ARCH_SPECIFIC__)) || \
     (defined(__CUDA_ARCH_FAMILY_SPECIFIC__)))
#define USE_TC 1
#else
#define USE_TC 0
#endif

#define NT     2048
#define HID    1024
#define INTERD 2048
#define NE     8
#define TK     2
#define NP     (NT*TK)
#define NPP    (NP + 128)

// ---- device scratch ----
__device__ __align__(16) __half g_Xp [NPP * HID];
__device__ __align__(16) __half g_Act[NPP * INTERD];
__device__ int   g_pair_token[NPP];
__device__ float g_pair_score[NPP];
__device__ int   g_counts[NE];
__device__ int   g_fill[NE];
__device__ int   g_offsets[NE + 1];
__device__ int   g_tok_e[NT * TK];
__device__ float g_tok_s[NT * TK];

#define SW128(o) ((o) ^ (((o) >> 3) & 0x70))

// ---------------------------------------------------------------------------
// small setup kernels
// ---------------------------------------------------------------------------
__global__ void zero_kernel(float* __restrict__ out) {
    int i = blockIdx.x * blockDim.x + threadIdx.x;
    if (i < NT * HID) out[i] = 0.0f;
    if (i < NE) { g_counts[i] = 0; g_fill[i] = 0; }
}

__global__ void route_kernel(const float* __restrict__ logits) {
    int t = blockIdx.x * blockDim.x + threadIdx.x;
    if (t >= NT) return;
    float l[NE];
#pragma unroll
    for (int i = 0; i < NE; i++) l[i] = logits[t * NE + i];
    int b0 = 0; float v0 = l[0];
#pragma unroll
    for (int i = 1; i < NE; i++) if (l[i] > v0) { v0 = l[i]; b0 = i; }
    int b1 = -1; float v1 = -1e30f;
#pragma unroll
    for (int i = 0; i < NE; i++) if (i != b0 && l[i] > v1) { v1 = l[i]; b1 = i; }
    float e1  = __expf(v1 - v0);
    float inv = 1.0f / (1.0f + e1);
    g_tok_e[t * 2 + 0] = b0; g_tok_s[t * 2 + 0] = inv;
    g_tok_e[t * 2 + 1] = b1; g_tok_s[t * 2 + 1] = e1 * inv;
    atomicAdd(&g_counts[b0], 1);
    atomicAdd(&g_counts[b1], 1);
}

__global__ void offsets_kernel() {
    if (threadIdx.x == 0) {
        int s = 0;
#pragma unroll
        for (int e = 0; e < NE; e++) { g_offsets[e] = s; s += g_counts[e]; }
        g_offsets[NE] = s;
    }
}

__global__ void scatter_kernel() {
    int t = blockIdx.x * blockDim.x + threadIdx.x;
    if (t >= NT) return;
#pragma unroll
    for (int k = 0; k < TK; k++) {
        int e = g_tok_e[t * 2 + k];
        int pos = g_offsets[e] + atomicAdd(&g_fill[e], 1);
        g_pair_token[pos] = t;
        g_pair_score[pos] = g_tok_s[t * 2 + k];
    }
}

__global__ void permute_kernel(const float* __restrict__ X) {
    int r = blockIdx.x;
    int t = g_pair_token[r];
    int c = threadIdx.x * 8;
    const float4* s = (const float4*)(X + (size_t)t * HID + c);
    float4 v0 = s[0], v1 = s[1];
    union { __half h[8]; uint4 u; } cv;
    cv.h[0] = __float2half_rn(v0.x); cv.h[1] = __float2half_rn(v0.y);
    cv.h[2] = __float2half_rn(v0.z); cv.h[3] = __float2half_rn(v0.w);
    cv.h[4] = __float2half_rn(v1.x); cv.h[5] = __float2half_rn(v1.y);
    cv.h[6] = __float2half_rn(v1.z); cv.h[7] = __float2half_rn(v1.w);
    *(uint4*)(g_Xp + (size_t)r * HID + c) = cv.u;
}

// ---------------------------------------------------------------------------
// tcgen05 helpers (compiled only in the arch-specific pass)
// ---------------------------------------------------------------------------
#if USE_TC
__device__ __forceinline__ uint32_t elect_one() {
    uint32_t p;
    asm volatile("{\n\t.reg .pred p;\n\telect.sync _|p, 0xFFFFFFFF;\n\t"
                 "selp.b32 %0,1,0,p;\n\t}" : "=r"(p));
    return p;
}
__device__ __forceinline__ void mbar_init(uint32_t a, uint32_t c) {
    asm volatile("mbarrier.init.shared.b64 [%0], %1;" :: "r"(a), "r"(c) : "memory");
}
__device__ __forceinline__ void mbar_wait(uint32_t a, uint32_t par) {
    asm volatile("{\n\t.reg .pred P;\n\tWL_%=:\n\t"
                 "mbarrier.try_wait.parity.acquire.cta.shared::cta.b64 P, [%0], %1, 0x989680;\n\t"
                 "@P bra WD_%=;\n\tbra WL_%=;\n\tWD_%=:\n\t}"
                 :: "r"(a), "r"(par) : "memory");
}
__device__ __forceinline__ void tc_alloc(uint32_t slot, uint32_t n) {
    asm volatile("tcgen05.alloc.cta_group::1.sync.aligned.shared::cta.b32 [%0], %1;"
                 :: "r"(slot), "r"(n) : "memory");
}
__device__ __forceinline__ void tc_relinquish() {
    asm volatile("tcgen05.relinquish_alloc_permit.cta_group::1.sync.aligned;");
}
__device__ __forceinline__ void tc_dealloc(uint32_t t, uint32_t n) {
    asm volatile("tcgen05.dealloc.cta_group::1.sync.aligned.b32 %0, %1;" :: "r"(t), "r"(n));
}
__device__ __forceinline__ void tc_commit(uint32_t mbar) {
    asm volatile("tcgen05.commit.cta_group::1.mbarrier::arrive::one.shared::cluster.b64 [%0];"
                 :: "r"(mbar) : "memory");
}
__device__ __forceinline__ void tc_mma_f16_ss(uint32_t d, uint64_t ad, uint64_t bd,
                                              uint32_t idesc, uint32_t en) {
    asm volatile("{\n\t.reg .pred p;\n\tsetp.ne.u32 p, %4, 0;\n\t"
                 "tcgen05.mma.cta_group::1.kind::f16 [%0], %1, %2, %3, {%5,%5,%5,%5}, p;\n\t}"
                 :: "r"(d), "l"(ad), "l"(bd), "r"(idesc), "r"(en), "r"(0u) : "memory");
}
__device__ __forceinline__ void tc_fence_after()  { asm volatile("tcgen05.fence::after_thread_sync;"  ::: "memory"); }
__device__ __forceinline__ void tc_fence_before() { asm volatile("tcgen05.fence::before_thread_sync;" ::: "memory"); }
__device__ __forceinline__ void tc_wait_ld()      { asm volatile("tcgen05.wait::ld.sync.aligned;"     ::: "memory"); }
__device__ __forceinline__ void fence_async_smem(){ asm volatile("fence.proxy.async.shared::cta;"     ::: "memory"); }

#define LDTM_X32(r, tmem_addr) \
    asm volatile( \
        "tcgen05.ld.sync.aligned.32x32b.x32.b32 " \
        "{%0, %1, %2, %3, %4, %5, %6, %7, " \
        " %8, %9, %10, %11, %12, %13, %14, %15, " \
        " %16, %17, %18, %19, %20, %21, %22, %23, " \
        " %24, %25, %26, %27, %28, %29, %30, %31}, [%32];" \
        : "=r"((r)[0]),  "=r"((r)[1]),  "=r"((r)[2]),  "=r"((r)[3]), \
          "=r"((r)[4]),  "=r"((r)[5]),  "=r"((r)[6]),  "=r"((r)[7]), \
          "=r"((r)[8]),  "=r"((r)[9]),  "=r"((r)[10]), "=r"((r)[11]), \
          "=r"((r)[12]), "=r"((r)[13]), "=r"((r)[14]), "=r"((r)[15]), \
          "=r"((r)[16]), "=r"((r)[17]), "=r"((r)[18]), "=r"((r)[19]), \
          "=r"((r)[20]), "=r"((r)[21]), "=r"((r)[22]), "=r"((r)[23]), \
          "=r"((r)[24]), "=r"((r)[25]), "=r"((r)[26]), "=r"((r)[27]), \
          "=r"((r)[28]), "=r"((r)[29]), "=r"((r)[30]), "=r"((r)[31]) \
        : "r"(tmem_addr))

// SMEM matrix descriptor: K-major SW128 (LBO=1, SBO=64, version=1, layout=2)
__device__ __forceinline__ uint64_t desc_k(uint32_t a) {
    return 0x4000404000010000ull | ((a >> 4) & 0x3FFF);
}
// idesc kind::f16: c=f32 (bit4), a=f16 K-major, b=f16 K-major, N=64 (8<<17),
// M=128 (8<<24). NO TransB — B is stored [N,K] K-major.
#define MMA_IDESC 0x8100010u
#endif // USE_TC

#if !USE_TC
#define MMA_OP(ACC, AF, B0, B1)                                               \
    asm volatile("mma.sync.aligned.m16n8k16.row.col.f32.f16.f16.f32 "         \
        "{%0,%1,%2,%3}, {%4,%5,%6,%7}, {%8,%9}, {%0,%1,%2,%3};"               \
        : "+f"(ACC[0]), "+f"(ACC[1]), "+f"(ACC[2]), "+f"(ACC[3])              \
        : "r"(AF[0]), "r"(AF[1]), "r"(AF[2]), "r"(AF[3]), "r"(B0), "r"(B1))
#endif

// ---------------------------------------------------------------------------
// Grouped GEMM. Unified launch geometry for both code paths:
//   256 threads; MODE 0 (FC1+SwiGLU): grid (32, mTiles, 8), 64 act cols/block
//   MODE 1 (FC2):                     grid (16, mTiles, 8), 64 out cols/block
// ---------------------------------------------------------------------------
template <int MODE>
__global__ __launch_bounds__(256)
void moe_gemm_kernel(const float* __restrict__ W, float* __restrict__ outp) {
    const int e   = blockIdx.z;
    const int cnt = g_counts[e];
    const int mt  = blockIdx.y;
    if (mt * 128 >= cnt) return;
    const int bn      = blockIdx.x;
    const int rowbase = g_offsets[e] + mt * 128;
    const int rowlim  = g_offsets[e] + cnt;

    constexpr int K   = MODE ? INTERD : HID;
    constexpr int LDB = MODE ? HID : 2 * INTERD;
    const __half* __restrict__ Ag = MODE ? g_Act : g_Xp;
    const float*  __restrict__ Wg = W + (size_t)e * K * LDB;

    extern __shared__ __align__(1024) char smem[];
    const int tid = threadIdx.x, wid = tid >> 5, lane = tid & 31;

#if USE_TC
    // =====================  tcgen05 path  =====================
    constexpr int KT     = K / 64;
    constexpr int NR     = MODE ? 1 : 2;            // B regions (proj[,gate])
    constexpr int TCOLS  = MODE ? 64 : 128;
    constexpr int ABYTES = 16384, BBYTES = 8192;
    constexpr int BOFF   = 2 * ABYTES;
    constexpr int CTRL   = BOFF + 2 * NR * BBYTES;

    uint32_t sbase = (uint32_t)__cvta_generic_to_shared(smem);
    uint32_t mb0 = sbase + CTRL + 8, mb1 = sbase + CTRL + 16;

    if (tid == 0) { mbar_init(mb0, 1); mbar_init(mb1, 1); }
    if (wid == 0) { tc_alloc(sbase + CTRL, TCOLS); tc_relinquish(); }
    __syncthreads();
    uint32_t tmem = *(volatile uint32_t*)(smem + CTRL);

    for (int kt = 0; kt < KT; kt++) {
        const int buf = kt & 1;
        if (kt >= 2) mbar_wait(buf ? mb1 : mb0, ((kt - 2) >> 1) & 1);
        const int k0 = kt * 64;
        {   // A tile: 128 rows x 64 k-halves, K-major SW128
            char* As = smem + buf * ABYTES;
            const __half* Ap = Ag + (size_t)rowbase * K + k0;
#pragma unroll
            for (int i = 0; i < 4; i++) {
                int u = i * 256 + tid, row = u >> 3, q = u & 7;
                uint4 v = *(const uint4*)(Ap + (size_t)row * K + q * 8);
                *(uint4*)(As + SW128(row * 128 + q * 16)) = v;
            }
        }
        // B tile(s): TRANSPOSED fill -> [64 n-rows][64 k-halves] K-major SW128.
        // Weights are n-contiguous [K][N]: lanes map to consecutive n
        // (coalesced reads); each thread packs 2 k-values into one STS.32.
#pragma unroll
        for (int r = 0; r < NR; r++) {
            char* Bs = smem + BOFF + (buf * NR + r) * BBYTES;
            const int colbase = (MODE == 0 && r == 1) ? (INTERD + bn * 64) : (bn * 64);
            const float* Bp = Wg + (size_t)k0 * LDB + colbase;
#pragma unroll
            for (int i = 0; i < 8; i++) {
                int u = i * 256 + tid;          // 0..2047
                int n = u & 63, kk2 = u >> 6;   // kk2 in 0..31 (pairs of k)
                float v0 = Bp[(size_t)(2 * kk2)     * LDB + n];
                float v1 = Bp[(size_t)(2 * kk2 + 1) * LDB + n];
                __half2 h = __floats2half2_rn(v0, v1);
                *(uint32_t*)(Bs + SW128(n * 128 + kk2 * 4)) = *(uint32_t*)&h;
            }
        }
        fence_async_smem();
        __syncthreads();
        if (wid == 0 && elect_one()) {
            uint64_t ad = desc_k(sbase + buf * ABYTES);
#pragma unroll
            for (int r = 0; r < NR; r++) {
                uint64_t bd = desc_k(sbase + BOFF + (buf * NR + r) * BBYTES);
#pragma unroll
                for (int k4 = 0; k4 < 4; k4++)   // 16-k step: +2 units (32B) in A and B
                    tc_mma_f16_ss(tmem + r * 64, ad + 2 * k4, bd + 2 * k4,
                                  MMA_IDESC, (kt > 0) || (k4 > 0));
            }
            tc_commit(buf ? mb1 : mb0);
        }
    }
    mbar_wait(((KT - 2) & 1) ? mb1 : mb0, ((KT - 2) >> 1) & 1);
    mbar_wait(((KT - 1) & 1) ? mb1 : mb0, ((KT - 1) >> 1) & 1);
    tc_fence_after();

    if (wid < 4) {                       // TMEM lanes: warp w -> rows w*32..
        const int m = rowbase + wid * 32 + lane;
        if (MODE == 0) {
#pragma unroll
            for (int pass = 0; pass < 2; pass++) {
                uint32_t dp[32], dg[32];
                LDTM_X32(dp, tmem + pass * 32);
                LDTM_X32(dg, tmem + 64 + pass * 32);
                tc_wait_ld();
                if (m < rowlim) {
                    uint32_t hh[16];
#pragma unroll
                    for (int j = 0; j < 32; j += 2) {
                        float p0 = __uint_as_float(dp[j]), p1 = __uint_as_float(dp[j + 1]);
                        float g0 = __uint_as_float(dg[j]), g1 = __uint_as_float(dg[j + 1]);
                        float a0 = p0 * g0 / (1.0f + __expf(-p0));
                        float a1 = p1 * g1 / (1.0f + __expf(-p1));
                        __half2 h = __floats2half2_rn(a0, a1);
                        hh[j >> 1] = *(uint32_t*)&h;
                    }
                    uint4* dst = (uint4*)(g_Act + (size_t)m * INTERD + bn * 64 + pass * 32);
#pragma unroll
                    for (int i = 0; i < 4; i++) dst[i] = ((uint4*)hh)[i];
                }
            }
        } else {
            int tkn = 0; float sc = 0.0f;
            if (m < rowlim) { tkn = g_pair_token[m]; sc = g_pair_score[m]; }
            float* orow = outp + (size_t)tkn * HID + bn * 64;
#pragma unroll
            for (int pass = 0; pass < 2; pass++) {
                uint32_t d[32];
                LDTM_X32(d, tmem + pass * 32);
                tc_wait_ld();
                if (m < rowlim) {
#pragma unroll
                    for (int j = 0; j < 32; j++)
                        atomicAdd(orow + pass * 32 + j, __uint_as_float(d[j]) * sc);
                }
            }
        }
        tc_fence_before();
    }
    __syncthreads();
    if (wid == 0) tc_dealloc(tmem, TCOLS);

#else
    // =====================  mma.sync fallback  =====================
    constexpr int BK   = 32;
    constexpr int KT   = K / BK;
    constexpr int BW   = MODE ? 72 : 136;       // B smem row width (+8 pad)
    constexpr int NGRP = MODE ? 2 : 4;          // 16-col B fragment groups
    constexpr int NBL  = MODE ? 2 : 4;          // B gmem loads per thread

    __half (*As)[128][40] = (__half(*)[128][40])smem;
    __half (*Bs)[BK][BW]  = (__half(*)[BK][BW])(smem + 2 * 128 * 40 * 2);

    const int wm = wid & 3;    // 4 warps along M (32 rows each)
    const int wn = wid >> 2;   // 2 warps along N

    int a_row[2], a_col[2];
#pragma unroll
    for (int i = 0; i < 2; i++) { int u = i * 256 + tid; a_row[i] = u >> 2; a_col[i] = (u & 3) * 8; }
    int b_row[NBL], b_sc[NBL], b_dc[NBL];
#pragma unroll
    for (int i = 0; i < NBL; i++) {
        int f = i * 256 + tid;
        if (MODE == 0) {
            int r = f >> 5, cs = f & 31;
            b_row[i] = r; b_dc[i] = cs * 4;
            b_sc[i] = (cs < 16) ? (bn * 64 + cs * 4) : (INTERD + bn * 64 + (cs - 16) * 4);
        } else {
            int r = f >> 4, cs = f & 15;
            b_row[i] = r; b_dc[i] = cs * 4;
            b_sc[i] = bn * 64 + cs * 4;
        }
    }

    float acc[2][2 * NGRP][4];
#pragma unroll
    for (int a = 0; a < 2; a++)
#pragma unroll
        for (int b = 0; b < 2 * NGRP; b++)
#pragma unroll
            for (int c = 0; c < 4; c++) acc[a][b][c] = 0.0f;

#pragma unroll
    for (int i = 0; i < 2; i++)
        *(uint4*)&As[0][a_row[i]][a_col[i]] =
            *(const uint4*)(Ag + (size_t)(rowbase + a_row[i]) * K + a_col[i]);
#pragma unroll
    for (int i = 0; i < NBL; i++) {
        float4 v = *(const float4*)(Wg + (size_t)b_row[i] * LDB + b_sc[i]);
        union { __half h[4]; uint2 u; } cv;
        cv.h[0] = __float2half_rn(v.x); cv.h[1] = __float2half_rn(v.y);
        cv.h[2] = __float2half_rn(v.z); cv.h[3] = __float2half_rn(v.w);
        *(uint2*)&Bs[0][b_row[i]][b_dc[i]] = cv.u;
    }
    __syncthreads();

    for (int kt = 0; kt < KT; kt++) {
        const int cur = kt & 1;
        uint4 aR[2]; float4 bR[NBL];
        const bool pf = (kt + 1 < KT);
        if (pf) {
            const int k0 = (kt + 1) * BK;
#pragma unroll
            for (int i = 0; i < 2; i++)
                aR[i] = *(const uint4*)(Ag + (size_t)(rowbase + a_row[i]) * K + k0 + a_col[i]);
#pragma unroll
            for (int i = 0; i < NBL; i++)
                bR[i] = *(const float4*)(Wg + (size_t)(k0 + b_row[i]) * LDB + b_sc[i]);
        }
#pragma unroll
        for (int ks = 0; ks < BK; ks += 16) {
            uint32_t af[2][4];
#pragma unroll
            for (int mf = 0; mf < 2; mf++) {
                const __half* p = &As[cur][wm * 32 + mf * 16 + (lane & 15)][ks + (lane >> 4) * 8];
                uint32_t sp = (uint32_t)__cvta_generic_to_shared(p);
                asm volatile("ldmatrix.sync.aligned.m8n8.x4.shared.b16 {%0,%1,%2,%3}, [%4];"
                    : "=r"(af[mf][0]), "=r"(af[mf][1]), "=r"(af[mf][2]), "=r"(af[mf][3]) : "r"(sp));
            }
            uint32_t bf[NGRP][4];
#pragma unroll
            for (int g = 0; g < NGRP; g++) {
                int bcol = (MODE == 0)
                    ? ((g < 2) ? (wn * 32 + g * 16) : (64 + wn * 32 + (g - 2) * 16))
                    : (wn * 32 + g * 16);
                const __half* p = &Bs[cur][ks + (lane & 15)][bcol + (lane >> 4) * 8];
                uint32_t sp = (uint32_t)__cvta_generic_to_shared(p);
                asm volatile("ldmatrix.sync.aligned.m8n8.x4.trans.shared.b16 {%0,%1,%2,%3}, [%4];"
                    : "=r"(bf[g][0]), "=r"(bf[g][1]), "=r"(bf[g][2]), "=r"(bf[g][3]) : "r"(sp));
            }
#pragma unroll
            for (int mf = 0; mf < 2; mf++) {
#pragma unroll
                for (int g = 0; g < NGRP; g++) {
                    MMA_OP(acc[mf][2 * g],     af[mf], bf[g][0], bf[g][1]);
                    MMA_OP(acc[mf][2 * g + 1], af[mf], bf[g][2], bf[g][3]);
                }
            }
        }
        if (pf) {
#pragma unroll
            for (int i = 0; i < 2; i++)
                *(uint4*)&As[cur ^ 1][a_row[i]][a_col[i]] = aR[i];
#pragma unroll
            for (int i = 0; i < NBL; i++) {
                union { __half h[4]; uint2 u; } cv;
                cv.h[0] = __float2half_rn(bR[i].x); cv.h[1] = __float2half_rn(bR[i].y);
                cv.h[2] = __float2half_rn(bR[i].z); cv.h[3] = __float2half_rn(bR[i].w);
                *(uint2*)&Bs[cur ^ 1][b_row[i]][b_dc[i]] = cv.u;
            }
        }
        __syncthreads();
    }

    if (MODE == 0) {
#pragma unroll
        for (int mf = 0; mf < 2; mf++) {
            int rb = rowbase + wm * 32 + mf * 16 + (lane >> 2);
#pragma unroll
            for (int h = 0; h < 2; h++) {
                int row = rb + h * 8;
                if (row < rowlim) {
#pragma unroll
                    for (int j = 0; j < 4; j++) {
                        float p0 = acc[mf][j][2 * h],     p1 = acc[mf][j][2 * h + 1];
                        float g0 = acc[mf][j + 4][2 * h], g1 = acc[mf][j + 4][2 * h + 1];
                        float a0 = p0 / (1.0f + __expf(-p0)) * g0;
                        float a1 = p1 / (1.0f + __expf(-p1)) * g1;
                        int col = bn * 64 + wn * 32 + j * 8 + (lane & 3) * 2;
                        *(__half2*)(g_Act + (size_t)row * INTERD + col) = __floats2half2_rn(a0, a1);
                    }
                }
            }
        }
    } else {
#pragma unroll
        for (int mf = 0; mf < 2; mf++) {
            int rb = rowbase + wm * 32 + mf * 16 + (lane >> 2);
#pragma unroll
            for (int h = 0; h < 2; h++) {
                int row = rb + h * 8;
                if (row < rowlim) {
                    int   tkn = g_pair_token[row];
                    float sc  = g_pair_score[row];
                    float* orow = outp + (size_t)tkn * HID;
#pragma unroll
                    for (int nf = 0; nf < 4; nf++) {
                        int col = bn * 64 + wn * 32 + nf * 8 + (lane & 3) * 2;
                        atomicAdd(&orow[col],     acc[mf][nf][2 * h] * sc);
                        atomicAdd(&orow[col + 1], acc[mf][nf][2 * h + 1] * sc);
                    }
                }
            }
        }
    }
#endif // USE_TC
}

// ---------------------------------------------------------------------------
extern "C" void kernel_launch(void* const* d_in, const int* in_sizes, int n_in,
                              void* d_out, int out_size) {
    const float* X      = (const float*)d_in[0];  // [2048,1024]
    const float* logits = (const float*)d_in[1];  // [2048,8]
    const float* w1     = (const float*)d_in[2];  // [8,1024,4096]
    const float* w2     = (const float*)d_in[3];  // [8,2048,1024]
    float* out          = (float*)d_out;          // [2048,1024]

    constexpr int SMEM1 = 2 * 16384 + 4 * 8192 + 24;  // 65560
    constexpr int SMEM2 = 2 * 16384 + 2 * 8192 + 24;  // 49176
    cudaFuncSetAttribute(moe_gemm_kernel<0>, cudaFuncAttributeMaxDynamicSharedMemorySize, SMEM1);
    cudaFuncSetAttribute(moe_gemm_kernel<1>, cudaFuncAttributeMaxDynamicSharedMemorySize, SMEM2);

    zero_kernel<<<(NT * HID + 255) / 256, 256>>>(out);
    route_kernel<<<(NT + 255) / 256, 256>>>(logits);
    offsets_kernel<<<1, 32>>>();
    scatter_kernel<<<(NT + 255) / 256, 256>>>();
    permute_kernel<<<NP, 128>>>(X);

    // FC1 (+SwiGLU): 32 n-tiles of 64 act cols (proj+gate paired)
    moe_gemm_kernel<0><<<dim3(32, 32, NE), 256, SMEM1>>>(w1, nullptr);
    // FC2: 16 n-tiles of 64 out cols
    moe_gemm_kernel<1><<<dim3(16, 32, NE), 256, SMEM2>>>(w2, out);
}

// round 7
// speedup vs baseline: 1.1726x; 1.1726x over previous
#include <cuda_runtime.h>
#include <cuda_fp16.h>
#include <cstdint>

// ---------------------------------------------------------------------------
// MoE (AriaExperts): top-2 routing + grouped tcgen05 f16 GEMM (SwiGLU fused)
// tokens=2048, hidden=1024, inter=2048, experts=8, topk=2
//
// R7: per-call weight transpose->fp16 pass (k-contiguous), cp.async fills with
// one-chunk lookahead, BM=256 per CTA (2 M=128 blocks sharing B tiles).
// tcgen05 MMA config (K-major SW128 SS, idesc 0x8100010) unchanged from the
// validated R6 kernel. Naive-correct fallback for the generic compile pass.
// ---------------------------------------------------------------------------

#if defined(__CUDA_ARCH__) && \
    (defined(__CUDA_ARCH_FEAT_SM103_ALL) || \
     (defined(__CUDA_ARCH_SPECIFIC__)) || \
     (defined(__CUDA_ARCH_FAMILY_SPECIFIC__)))
#define USE_TC 1
#else
#define USE_TC 0
#endif

#define NT     2048
#define HID    1024
#define INTERD 2048
#define NE     8
#define TK     2
#define NP     (NT*TK)
#define NPP    (NP + 256)    // BM=256 tile overrun padding

// ---- device scratch ----
__device__ __align__(16) __half g_Xp [NPP * HID];
__device__ __align__(16) __half g_Act[NPP * INTERD];
__device__ __align__(16) __half g_W1h[NE * 2 * INTERD * HID];   // [E][4096][1024]
__device__ __align__(16) __half g_W2h[NE * HID * INTERD];       // [E][1024][2048]
__device__ int   g_pair_token[NPP];
__device__ float g_pair_score[NPP];
__device__ int   g_counts[NE];
__device__ int   g_fill[NE];
__device__ int   g_offsets[NE + 1];
__device__ int   g_tok_e[NT * TK];
__device__ float g_tok_s[NT * TK];

#define SW128(o) ((o) ^ (((o) >> 3) & 0x70))

// ---------------------------------------------------------------------------
// small setup kernels
// ---------------------------------------------------------------------------
__global__ void zero_kernel(float* __restrict__ out) {
    int i = blockIdx.x * blockDim.x + threadIdx.x;
    if (i < NT * HID) out[i] = 0.0f;
    if (i < NE) { g_counts[i] = 0; g_fill[i] = 0; }
}

__global__ void route_kernel(const float* __restrict__ logits) {
    int t = blockIdx.x * blockDim.x + threadIdx.x;
    if (t >= NT) return;
    float l[NE];
#pragma unroll
    for (int i = 0; i < NE; i++) l[i] = logits[t * NE + i];
    int b0 = 0; float v0 = l[0];
#pragma unroll
    for (int i = 1; i < NE; i++) if (l[i] > v0) { v0 = l[i]; b0 = i; }
    int b1 = -1; float v1 = -1e30f;
#pragma unroll
    for (int i = 0; i < NE; i++) if (i != b0 && l[i] > v1) { v1 = l[i]; b1 = i; }
    float e1  = __expf(v1 - v0);
    float inv = 1.0f / (1.0f + e1);
    g_tok_e[t * 2 + 0] = b0; g_tok_s[t * 2 + 0] = inv;
    g_tok_e[t * 2 + 1] = b1; g_tok_s[t * 2 + 1] = e1 * inv;
    atomicAdd(&g_counts[b0], 1);
    atomicAdd(&g_counts[b1], 1);
}

__global__ void offsets_kernel() {
    if (threadIdx.x == 0) {
        int s = 0;
#pragma unroll
        for (int e = 0; e < NE; e++) { g_offsets[e] = s; s += g_counts[e]; }
        g_offsets[NE] = s;
    }
}

__global__ void scatter_kernel() {
    int t = blockIdx.x * blockDim.x + threadIdx.x;
    if (t >= NT) return;
#pragma unroll
    for (int k = 0; k < TK; k++) {
        int e = g_tok_e[t * 2 + k];
        int pos = g_offsets[e] + atomicAdd(&g_fill[e], 1);
        g_pair_token[pos] = t;
        g_pair_score[pos] = g_tok_s[t * 2 + k];
    }
}

__global__ void permute_kernel(const float* __restrict__ X) {
    int r = blockIdx.x;
    int t = g_pair_token[r];
    int c = threadIdx.x * 8;
    const float4* s = (const float4*)(X + (size_t)t * HID + c);
    float4 v0 = s[0], v1 = s[1];
    union { __half h[8]; uint4 u; } cv;
    cv.h[0] = __float2half_rn(v0.x); cv.h[1] = __float2half_rn(v0.y);
    cv.h[2] = __float2half_rn(v0.z); cv.h[3] = __float2half_rn(v0.w);
    cv.h[4] = __float2half_rn(v1.x); cv.h[5] = __float2half_rn(v1.y);
    cv.h[6] = __float2half_rn(v1.z); cv.h[7] = __float2half_rn(v1.w);
    *(uint4*)(g_Xp + (size_t)r * HID + c) = cv.u;
}

// ---------------------------------------------------------------------------
// Weight transpose + fp32->fp16:  in [e][K][N] f32  ->  out [e][N][K] f16
// 32x32 tiles, block (32,8), classic smem transpose.
// ---------------------------------------------------------------------------
__global__ void convT_kernel(const float* __restrict__ in, __half* __restrict__ out,
                             int K, int N) {
    __shared__ float tile[32][33];
    const int e  = blockIdx.z;
    const int n0 = blockIdx.x * 32, k0 = blockIdx.y * 32;
    const float* ip = in  + (size_t)e * K * N;
    __half*      op = out + (size_t)e * N * K;
    const int tx = threadIdx.x, ty = threadIdx.y;
#pragma unroll
    for (int i = 0; i < 4; i++)
        tile[ty + i * 8][tx] = ip[(size_t)(k0 + ty + i * 8) * N + n0 + tx];
    __syncthreads();
#pragma unroll
    for (int i = 0; i < 4; i++)
        op[(size_t)(n0 + ty + i * 8) * K + k0 + tx] =
            __float2half_rn(tile[tx][ty + i * 8]);
}

// ---------------------------------------------------------------------------
// tcgen05 helpers (arch-specific pass only)
// ---------------------------------------------------------------------------
#if USE_TC
__device__ __forceinline__ uint32_t elect_one() {
    uint32_t p;
    asm volatile("{\n\t.reg .pred p;\n\telect.sync _|p, 0xFFFFFFFF;\n\t"
                 "selp.b32 %0,1,0,p;\n\t}" : "=r"(p));
    return p;
}
__device__ __forceinline__ void mbar_init(uint32_t a, uint32_t c) {
    asm volatile("mbarrier.init.shared.b64 [%0], %1;" :: "r"(a), "r"(c) : "memory");
}
__device__ __forceinline__ void mbar_wait(uint32_t a, uint32_t par) {
    asm volatile("{\n\t.reg .pred P;\n\tWL_%=:\n\t"
                 "mbarrier.try_wait.parity.acquire.cta.shared::cta.b64 P, [%0], %1, 0x989680;\n\t"
                 "@P bra WD_%=;\n\tbra WL_%=;\n\tWD_%=:\n\t}"
                 :: "r"(a), "r"(par) : "memory");
}
__device__ __forceinline__ void tc_alloc(uint32_t slot, uint32_t n) {
    asm volatile("tcgen05.alloc.cta_group::1.sync.aligned.shared::cta.b32 [%0], %1;"
                 :: "r"(slot), "r"(n) : "memory");
}
__device__ __forceinline__ void tc_relinquish() {
    asm volatile("tcgen05.relinquish_alloc_permit.cta_group::1.sync.aligned;");
}
__device__ __forceinline__ void tc_dealloc(uint32_t t, uint32_t n) {
    asm volatile("tcgen05.dealloc.cta_group::1.sync.aligned.b32 %0, %1;" :: "r"(t), "r"(n));
}
__device__ __forceinline__ void tc_commit(uint32_t mbar) {
    asm volatile("tcgen05.commit.cta_group::1.mbarrier::arrive::one.shared::cluster.b64 [%0];"
                 :: "r"(mbar) : "memory");
}
__device__ __forceinline__ void tc_mma_f16_ss(uint32_t d, uint64_t ad, uint64_t bd,
                                              uint32_t idesc, uint32_t en) {
    asm volatile("{\n\t.reg .pred p;\n\tsetp.ne.u32 p, %4, 0;\n\t"
                 "tcgen05.mma.cta_group::1.kind::f16 [%0], %1, %2, %3, {%5,%5,%5,%5}, p;\n\t}"
                 :: "r"(d), "l"(ad), "l"(bd), "r"(idesc), "r"(en), "r"(0u) : "memory");
}
__device__ __forceinline__ void tc_fence_after()  { asm volatile("tcgen05.fence::after_thread_sync;"  ::: "memory"); }
__device__ __forceinline__ void tc_fence_before() { asm volatile("tcgen05.fence::before_thread_sync;" ::: "memory"); }
__device__ __forceinline__ void tc_wait_ld()      { asm volatile("tcgen05.wait::ld.sync.aligned;"     ::: "memory"); }
__device__ __forceinline__ void fence_async_smem(){ asm volatile("fence.proxy.async.shared::cta;"     ::: "memory"); }
__device__ __forceinline__ void cp16(uint32_t dst, const void* src) {
    asm volatile("cp.async.cg.shared.global [%0], [%1], 16;" :: "r"(dst), "l"(src));
}
__device__ __forceinline__ void cp_commit() { asm volatile("cp.async.commit_group;" ::: "memory"); }
template <int N> __device__ __forceinline__ void cp_wait() {
    asm volatile("cp.async.wait_group %0;" :: "n"(N) : "memory");
}

#define LDTM_X32(r, tmem_addr) \
    asm volatile( \
        "tcgen05.ld.sync.aligned.32x32b.x32.b32 " \
        "{%0, %1, %2, %3, %4, %5, %6, %7, " \
        " %8, %9, %10, %11, %12, %13, %14, %15, " \
        " %16, %17, %18, %19, %20, %21, %22, %23, " \
        " %24, %25, %26, %27, %28, %29, %30, %31}, [%32];" \
        : "=r"((r)[0]),  "=r"((r)[1]),  "=r"((r)[2]),  "=r"((r)[3]), \
          "=r"((r)[4]),  "=r"((r)[5]),  "=r"((r)[6]),  "=r"((r)[7]), \
          "=r"((r)[8]),  "=r"((r)[9]),  "=r"((r)[10]), "=r"((r)[11]), \
          "=r"((r)[12]), "=r"((r)[13]), "=r"((r)[14]), "=r"((r)[15]), \
          "=r"((r)[16]), "=r"((r)[17]), "=r"((r)[18]), "=r"((r)[19]), \
          "=r"((r)[20]), "=r"((r)[21]), "=r"((r)[22]), "=r"((r)[23]), \
          "=r"((r)[24]), "=r"((r)[25]), "=r"((r)[26]), "=r"((r)[27]), \
          "=r"((r)[28]), "=r"((r)[29]), "=r"((r)[30]), "=r"((r)[31]) \
        : "r"(tmem_addr))

// SMEM matrix descriptor: K-major SW128 (LBO=1, SBO=64, version=1, layout=2)
__device__ __forceinline__ uint64_t desc_k(uint32_t a) {
    return 0x4000404000010000ull | ((a >> 4) & 0x3FFF);
}
// idesc kind::f16: c=f32, a=f16 K-major, b=f16 K-major, N=64, M=128 (validated R6)
#define MMA_IDESC 0x8100010u
#endif // USE_TC

// ---------------------------------------------------------------------------
// Grouped GEMM.  256 threads.
//   MODE 0 (FC1+SwiGLU): grid (32, 16, 8)  BM=256, 64 act cols (proj+gate)
//   MODE 1 (FC2):        grid (16, 16, 8)  BM=256, 64 out cols
// ---------------------------------------------------------------------------
template <int MODE>
__global__ __launch_bounds__(256)
void moe_gemm_kernel(float* __restrict__ outp) {
    const int e   = blockIdx.z;
    const int cnt = g_counts[e];
    const int mt  = blockIdx.y;
    if (mt * 256 >= cnt) return;
    const int bn      = blockIdx.x;
    const int rowbase = g_offsets[e] + mt * 256;
    const int rowlim  = g_offsets[e] + cnt;

    constexpr int K = MODE ? INTERD : HID;
    const __half* __restrict__ Ag = MODE ? g_Act : g_Xp;
    const __half* __restrict__ Wh = MODE
        ? (g_W2h + (size_t)e * HID * INTERD)          // [1024][2048]
        : (g_W1h + (size_t)e * 2 * INTERD * HID);     // [4096][1024]

    extern __shared__ __align__(1024) char smem[];
    const int tid = threadIdx.x, wid = tid >> 5, lane = tid & 31;

#if USE_TC
    // =====================  tcgen05 path  =====================
    constexpr int KT     = K / 64;
    constexpr int NR     = MODE ? 1 : 2;              // B regions (proj[,gate])
    constexpr int TCOLS  = MODE ? 128 : 256;          // 2 m-blocks
    constexpr int ABYTES = 16384, BBYTES = 8192;
    constexpr int BOFF   = 4 * ABYTES;                // 2 bufs x 2 mblk
    constexpr int CTRL   = BOFF + 2 * NR * BBYTES;

    uint32_t sbase = (uint32_t)__cvta_generic_to_shared(smem);
    uint32_t mb0 = sbase + CTRL + 8, mb1 = sbase + CTRL + 16;

    if (tid == 0) { mbar_init(mb0, 1); mbar_init(mb1, 1); }
    if (wid == 0) { tc_alloc(sbase + CTRL, TCOLS); tc_relinquish(); }
    __syncthreads();
    uint32_t tmem = *(volatile uint32_t*)(smem + CTRL);

    // chunk fill: A 2x(128 rows x 64k) + B NRx(64 n-rows x 64k), all K-major SW128
    auto fill_chunk = [&](int j) {
        const int buf = j & 1;
        const int k0  = j * 64;
#pragma unroll
        for (int mb = 0; mb < 2; mb++) {
            uint32_t As = sbase + (buf * 2 + mb) * ABYTES;
            const __half* Ap = Ag + (size_t)(rowbase + mb * 128) * K + k0;
#pragma unroll
            for (int i = 0; i < 4; i++) {
                int u = i * 256 + tid, row = u >> 3, q = u & 7;
                cp16(As + SW128(row * 128 + q * 16), Ap + (size_t)row * K + q * 8);
            }
        }
#pragma unroll
        for (int r = 0; r < NR; r++) {
            uint32_t Bs = sbase + BOFF + (buf * NR + r) * BBYTES;
            const int nb = (MODE == 0 && r == 1) ? (INTERD + bn * 64) : (bn * 64);
            const __half* Bp = Wh + (size_t)nb * K + k0;
#pragma unroll
            for (int i = 0; i < 2; i++) {
                int u = i * 256 + tid, row = u >> 3, q = u & 7;
                cp16(Bs + SW128(row * 128 + q * 16), Bp + (size_t)row * K + q * 8);
            }
        }
        cp_commit();
    };

    fill_chunk(0);
    for (int kt = 0; kt < KT; kt++) {
        const int buf = kt & 1;
        if (kt + 1 < KT) {
            if (kt + 1 >= 2)
                mbar_wait(((kt + 1) & 1) ? mb1 : mb0, (((kt + 1) - 2) >> 1) & 1);
            fill_chunk(kt + 1);
            cp_wait<1>();
        } else {
            cp_wait<0>();
        }
        fence_async_smem();
        __syncthreads();
        if (wid == 0 && elect_one()) {
#pragma unroll
            for (int mb = 0; mb < 2; mb++) {
                uint64_t ad = desc_k(sbase + (buf * 2 + mb) * ABYTES);
#pragma unroll
                for (int r = 0; r < NR; r++) {
                    uint64_t bd = desc_k(sbase + BOFF + (buf * NR + r) * BBYTES);
#pragma unroll
                    for (int k4 = 0; k4 < 4; k4++)   // 16-k step: +2 desc units
                        tc_mma_f16_ss(tmem + mb * (NR * 64) + r * 64,
                                      ad + 2 * k4, bd + 2 * k4,
                                      MMA_IDESC, (kt > 0) || (k4 > 0));
                }
            }
            tc_commit(buf ? mb1 : mb0);
        }
    }
    mbar_wait(mb0, ((KT - 2) >> 1) & 1);
    mbar_wait(mb1, ((KT - 1) >> 1) & 1);
    tc_fence_after();

    // epilogue: 8 warps cover 256 rows; warp -> mblk = wid>>2, subpartition wid&3
    {
        const int mb  = wid >> 2;
        const int m   = rowbase + mb * 128 + (wid & 3) * 32 + lane;
        const int cb  = mb * (MODE ? 64 : 128);   // TMEM col base for this m-block
        if (MODE == 0) {
#pragma unroll
            for (int pass = 0; pass < 2; pass++) {
                uint32_t dp[32], dg[32];
                LDTM_X32(dp, tmem + cb + pass * 32);
                LDTM_X32(dg, tmem + cb + 64 + pass * 32);
                tc_wait_ld();
                if (m < rowlim) {
                    uint32_t hh[16];
#pragma unroll
                    for (int j = 0; j < 32; j += 2) {
                        float p0 = __uint_as_float(dp[j]), p1 = __uint_as_float(dp[j + 1]);
                        float g0 = __uint_as_float(dg[j]), g1 = __uint_as_float(dg[j + 1]);
                        float a0 = p0 * g0 / (1.0f + __expf(-p0));
                        float a1 = p1 * g1 / (1.0f + __expf(-p1));
                        __half2 h = __floats2half2_rn(a0, a1);
                        hh[j >> 1] = *(uint32_t*)&h;
                    }
                    uint4* dst = (uint4*)(g_Act + (size_t)m * INTERD + bn * 64 + pass * 32);
#pragma unroll
                    for (int i = 0; i < 4; i++) dst[i] = ((uint4*)hh)[i];
                }
            }
        } else {
            int tkn = 0; float sc = 0.0f;
            if (m < rowlim) { tkn = g_pair_token[m]; sc = g_pair_score[m]; }
            float* orow = outp + (size_t)tkn * HID + bn * 64;
#pragma unroll
            for (int pass = 0; pass < 2; pass++) {
                uint32_t d[32];
                LDTM_X32(d, tmem + cb + pass * 32);
                tc_wait_ld();
                if (m < rowlim) {
#pragma unroll
                    for (int j = 0; j < 32; j++)
                        atomicAdd(orow + pass * 32 + j, __uint_as_float(d[j]) * sc);
                }
            }
        }
        tc_fence_before();
    }
    __syncthreads();
    if (wid == 0) tc_dealloc(tmem, TCOLS);

#else
    // ============ naive-correct fallback (insurance only) ============
    (void)smem; (void)wid; (void)lane;
    const int row = rowbase + tid;
    if (row >= rowlim) return;
    if (MODE == 0) {
        const __half* a = g_Xp + (size_t)row * HID;
        for (int j = 0; j < 64; j++) {
            const __half* wp = Wh + (size_t)(bn * 64 + j) * HID;
            const __half* wg = Wh + (size_t)(INTERD + bn * 64 + j) * HID;
            float p = 0.0f, g = 0.0f;
            for (int k = 0; k < HID; k++) {
                float av = __half2float(a[k]);
                p += av * __half2float(wp[k]);
                g += av * __half2float(wg[k]);
            }
            float act = p / (1.0f + __expf(-p)) * g;
            g_Act[(size_t)row * INTERD + bn * 64 + j] = __float2half_rn(act);
        }
    } else {
        const __half* a = g_Act + (size_t)row * INTERD;
        const int   tkn = g_pair_token[row];
        const float sc  = g_pair_score[row];
        for (int j = 0; j < 64; j++) {
            const __half* wp = Wh + (size_t)(bn * 64 + j) * INTERD;
            float s = 0.0f;
            for (int k = 0; k < INTERD; k++)
                s += __half2float(a[k]) * __half2float(wp[k]);
            atomicAdd(outp + (size_t)tkn * HID + bn * 64 + j, s * sc);
        }
    }
#endif // USE_TC
}

// ---------------------------------------------------------------------------
extern "C" void kernel_launch(void* const* d_in, const int* in_sizes, int n_in,
                              void* d_out, int out_size) {
    const float* X      = (const float*)d_in[0];  // [2048,1024]
    const float* logits = (const float*)d_in[1];  // [2048,8]
    const float* w1     = (const float*)d_in[2];  // [8,1024,4096]
    const float* w2     = (const float*)d_in[3];  // [8,2048,1024]
    float* out          = (float*)d_out;          // [2048,1024]

    __half* w1h = nullptr; __half* w2h = nullptr;
    cudaGetSymbolAddress((void**)&w1h, g_W1h);
    cudaGetSymbolAddress((void**)&w2h, g_W2h);

    constexpr int SMEM1 = 4 * 16384 + 4 * 8192 + 32;  // 98336
    constexpr int SMEM2 = 4 * 16384 + 2 * 8192 + 32;  // 81952
    cudaFuncSetAttribute(moe_gemm_kernel<0>, cudaFuncAttributeMaxDynamicSharedMemorySize, SMEM1);
    cudaFuncSetAttribute(moe_gemm_kernel<1>, cudaFuncAttributeMaxDynamicSharedMemorySize, SMEM2);

    // weight transpose + fp16 (every call; deterministic)
    convT_kernel<<<dim3(128, 32, NE), dim3(32, 8)>>>(w1, w1h, HID, 2 * INTERD);
    convT_kernel<<<dim3(32, 64, NE), dim3(32, 8)>>>(w2, w2h, INTERD, HID);

    zero_kernel<<<(NT * HID + 255) / 256, 256>>>(out);
    route_kernel<<<(NT + 255) / 256, 256>>>(logits);
    offsets_kernel<<<1, 32>>>();
    scatter_kernel<<<(NT + 255) / 256, 256>>>();
    permute_kernel<<<NP, 128>>>(X);

    // FC1 (+SwiGLU): 32 n-tiles of 64 act cols (proj+gate), BM=256
    moe_gemm_kernel<0><<<dim3(32, 16, NE), 256, SMEM1>>>(nullptr);
    // FC2: 16 n-tiles of 64 out cols, BM=256
    moe_gemm_kernel<1><<<dim3(16, 16, NE), 256, SMEM2>>>(out);
}